// round 5
// baseline (speedup 1.0000x reference)
#include <cuda_runtime.h>

#define BB   8
#define NPT  4096
#define DD   64
#define KP   1024
#define NNB  16
#define CC   128
#define CIN  67            // D + 3
#define MT   (BB*KP*NNB)   // 131072 rows
#define EPSBN 1e-5f

// ---------------- scratch ----------------
__device__ float g_h1[(size_t)MT*CC];
__device__ float g_h2[(size_t)MT*CC];
__device__ int   g_knn[MT];
__device__ float g_nxyz[BB*KP*3];
__device__ float g_W1T[CIN*CC];
__device__ float g_W2T[CC*CC];
__device__ float g_part[2*1024*CC];
__device__ float g_scale[2][CC];
__device__ float g_shift[2][CC];

// ---------------- helpers ----------------
__device__ __forceinline__ void fma2(unsigned long long& d, unsigned long long a, unsigned long long b) {
    asm("fma.rn.f32x2 %0,%1,%2,%0;" : "+l"(d) : "l"(a), "l"(b));
}
__device__ __forceinline__ unsigned long long mul2(unsigned long long a, unsigned long long b) {
    unsigned long long r; asm("mul.rn.f32x2 %0,%1,%2;" : "=l"(r) : "l"(a), "l"(b)); return r;
}
__device__ __forceinline__ unsigned long long add2(unsigned long long a, unsigned long long b) {
    unsigned long long r; asm("add.rn.f32x2 %0,%1,%2;" : "=l"(r) : "l"(a), "l"(b)); return r;
}
__device__ __forceinline__ unsigned long long pk2(float lo, float hi) {
    unsigned long long r; asm("mov.b64 %0,{%1,%2};" : "=l"(r) : "f"(lo), "f"(hi)); return r;
}
__device__ __forceinline__ float2 u2f(unsigned long long v) {
    float2 f; asm("mov.b64 {%0,%1},%2;" : "=f"(f.x), "=f"(f.y) : "l"(v)); return f;
}

// ---------------- FPS v5: value-only 32-bit butterflies + ballot index recovery ----------------
// Point mapping: global index p = tid*8 + i (contiguous per thread) so that
// lowest matching lane == lowest global index (exact jnp.argmax tie-break).
__global__ void fps_kernel(const float* __restrict__ xyz, float* __restrict__ outx) {
    extern __shared__ float fsm[];
    float* sx = fsm;
    float* sy = fsm + NPT;
    float* sz = fsm + 2*NPT;
    unsigned long long* slot = (unsigned long long*)(fsm + 3*NPT);  // [2][16]

    const int b    = blockIdx.x;
    const int tid  = threadIdx.x;            // 512
    const int lane = tid & 31, warp = tid >> 5;
    const float* base = xyz + (size_t)b*NPT*3;

    // load 8 consecutive points (24 floats) via 6 float4
    float c[24];
    {
        const float4* s4 = (const float4*)(base + tid*24);
#pragma unroll
        for (int q = 0; q < 6; q++) {
            float4 v = s4[q];
            c[4*q+0] = v.x; c[4*q+1] = v.y; c[4*q+2] = v.z; c[4*q+3] = v.w;
        }
    }
    unsigned long long pxp[4], pyp[4], pzp[4];
    float dist[8];
#pragma unroll
    for (int q = 0; q < 4; q++) {
        pxp[q] = pk2(c[6*q+0], c[6*q+3]);
        pyp[q] = pk2(c[6*q+1], c[6*q+4]);
        pzp[q] = pk2(c[6*q+2], c[6*q+5]);
        dist[2*q] = 1e10f; dist[2*q+1] = 1e10f;
    }
#pragma unroll
    for (int i = 0; i < 8; i++) {
        int p = tid*8 + i;
        sx[p] = c[3*i+0]; sy[p] = c[3*i+1]; sz[p] = c[3*i+2];
    }
    __syncthreads();

    int far = 0;
    for (int t = 0; t < KP; t++) {
        float cx = sx[far], cy = sy[far], cz = sz[far];
        if (tid == 0) {
            int o = (b*KP + t)*3;
            g_nxyz[o+0] = cx; g_nxyz[o+1] = cy; g_nxyz[o+2] = cz;
            if (outx) { outx[o+0] = cx; outx[o+1] = cy; outx[o+2] = cz; }
        }
        unsigned long long ncx = pk2(-cx, -cx), ncy = pk2(-cy, -cy), ncz = pk2(-cz, -cz);
#pragma unroll
        for (int q = 0; q < 4; q++) {
            unsigned long long dx = add2(pxp[q], ncx);
            unsigned long long dy = add2(pyp[q], ncy);
            unsigned long long dz = add2(pzp[q], ncz);
            unsigned long long dd = mul2(dx, dx);
            fma2(dd, dy, dy);
            fma2(dd, dz, dz);
            float2 e = u2f(dd);
            dist[2*q]   = fminf(dist[2*q],   e.x);
            dist[2*q+1] = fminf(dist[2*q+1], e.y);
        }
        // thread-local max (value only)
        float t01 = fmaxf(dist[0], dist[1]), t23 = fmaxf(dist[2], dist[3]);
        float t45 = fmaxf(dist[4], dist[5]), t67 = fmaxf(dist[6], dist[7]);
        float tm = fmaxf(fmaxf(t01, t23), fmaxf(t45, t67));
        // 5-level value-only butterfly
        float m = tm;
#pragma unroll
        for (int o = 16; o > 0; o >>= 1)
            m = fmaxf(m, __shfl_xor_sync(0xffffffffu, m, o));
        // index recovery: lowest slot within thread, lowest lane across warp
        int li = 7;
#pragma unroll
        for (int i = 6; i >= 0; i--) li = (dist[i] == m) ? i : li;
        unsigned g = (unsigned)(tid*8 + li);
        unsigned mask = __ballot_sync(0xffffffffu, tm == m);
        unsigned widx = __shfl_sync(0xffffffffu, g, __ffs(mask) - 1);
        const int par = (t & 1) * 16;
        if (lane == 0)
            slot[par + warp] = ((unsigned long long)__float_as_uint(m) << 32) | widx;
        __syncthreads();
        // phase 2: all warps redundantly (no second barrier)
        unsigned long long kk = slot[par + (lane & 15)];
        unsigned val = (unsigned)(kk >> 32), idx = (unsigned)kk;
        unsigned vm = val;
#pragma unroll
        for (int o = 8; o > 0; o >>= 1)
            vm = max(vm, __shfl_xor_sync(0xffffffffu, vm, o));
        unsigned m2 = __ballot_sync(0xffffffffu, val == vm) & 0xFFFFu;
        if (__popc(m2) > 1) {   // warp-uniform rare path: exact min-index over ties
            unsigned cand = (val == vm && lane < 16) ? idx : 0xFFFFFFFFu;
#pragma unroll
            for (int o = 8; o > 0; o >>= 1)
                cand = min(cand, __shfl_xor_sync(0xffffffffu, cand, o));
            far = (int)cand;
        } else {
            far = (int)__shfl_sync(0xffffffffu, idx, __ffs(m2) - 1);
        }
    }
}

// ---------------- kNN: one warp per center ----------------
__global__ void knn_kernel(const float* __restrict__ xyz) {
    extern __shared__ float sm[];
    float* spx = sm;
    float* spy = sm + NPT;
    float* spz = sm + 2*NPT;
    float* sn  = sm + 3*NPT;

    int cid0 = blockIdx.x * 4;
    int b    = cid0 >> 10;
    const float* base = xyz + (size_t)b*NPT*3;
    for (int j = threadIdx.x; j < NPT; j += 128) {
        float x = base[j*3+0], y = base[j*3+1], z = base[j*3+2];
        spx[j] = x; spy[j] = y; spz[j] = z;
        sn[j]  = x*x + y*y + z*z;
    }
    __syncthreads();

    int w = threadIdx.x >> 5, l = threadIdx.x & 31;
    int cid = cid0 + w;
    float cx = g_nxyz[cid*3+0], cy = g_nxyz[cid*3+1], cz = g_nxyz[cid*3+2];
    float cn = cx*cx + cy*cy + cz*cz;

    float bd[16]; int bi[16];
#pragma unroll
    for (int k = 0; k < 16; k++) { bd[k] = 3.4e38f; bi[k] = 1 << 30; }

    for (int j = l; j < NPT; j += 32) {
        float dot = cx*spx[j] + cy*spy[j] + cz*spz[j];
        float sq  = cn + sn[j] - 2.0f*dot;
        if (sq < bd[15] || (sq == bd[15] && j < bi[15])) {
            float d = sq; int ii = j;
#pragma unroll
            for (int k = 0; k < 16; k++) {
                bool sw = (d < bd[k]) || (d == bd[k] && ii < bi[k]);
                float td = bd[k]; int ti = bi[k];
                if (sw) { bd[k] = d; bi[k] = ii; d = td; ii = ti; }
            }
        }
    }
    for (int s = 0; s < 16; s++) {
        float v = bd[0]; int vi = bi[0];
#pragma unroll
        for (int o = 16; o > 0; o >>= 1) {
            float ov = __shfl_xor_sync(0xffffffffu, v, o);
            int   oi = __shfl_xor_sync(0xffffffffu, vi, o);
            if (ov < v || (ov == v && oi < vi)) { v = ov; vi = oi; }
        }
        if (bd[0] == v && bi[0] == vi) {
#pragma unroll
            for (int k = 0; k < 15; k++) { bd[k] = bd[k+1]; bi[k] = bi[k+1]; }
            bd[15] = 3.4e38f; bi[15] = 1 << 30;
        }
        if (l == 0) g_knn[cid*16 + s] = vi;
    }
}

// ---------------- pre-transpose weights (k-major) ----------------
__global__ void wt_kernel(const float* __restrict__ W1, const float* __restrict__ W2) {
    for (int idx = threadIdx.x; idx < CC*CIN; idx += blockDim.x) {
        int o = idx / CIN, c = idx - o*CIN;
        g_W1T[c*CC + o] = W1[idx];
    }
    for (int idx = threadIdx.x; idx < CC*CC; idx += blockDim.x) {
        int o = idx >> 7, c = idx & 127;
        g_W2T[c*CC + o] = W2[idx];
    }
}

#define SAST 132   // scalar A tile stride (floats)

// stats epilogue: per-block column sum/sumsq -> g_part (reuses sA region)
__device__ __forceinline__ void stats_epilogue(float* red, const float s8[8], const float q8[8],
                                               int ty, int tx, int tid, int blk) {
#pragma unroll
    for (int j = 0; j < 8; j++) {
        red[ty*256 + tx*8 + j]       = s8[j];
        red[ty*256 + 128 + tx*8 + j] = q8[j];
    }
    __syncthreads();
    if (tid < 128) {
        float s = 0.0f, q = 0.0f;
#pragma unroll
        for (int y = 0; y < 16; y++) {
            s += red[y*256 + tid];
            q += red[y*256 + 128 + tid];
        }
        g_part[blk*CC + tid]           = s;
        g_part[1024*CC + blk*CC + tid] = q;
    }
}

// ---------------- GEMM1 (fused gather + stats) ----------------
__global__ void __launch_bounds__(256, 2) gemm1_kernel(const float* __restrict__ xyz,
                             const float* __restrict__ points,
                             const float* __restrict__ bias) {
    extern __shared__ float sm[];
    float* sA = sm;                           // CIN * SAST
    float* sB = sm + CIN*SAST;                // CIN * 128
    __shared__ int   s_nid[128];
    __shared__ float s_ctr[128*3];

    const int m0 = blockIdx.x * 128;
    const int tid = threadIdx.x;              // 256

    if (tid < 128) {
        int gw = m0 + tid;
        s_nid[tid] = g_knn[gw];
        int bk = gw >> 4;
        s_ctr[tid*3+0] = g_nxyz[bk*3+0];
        s_ctr[tid*3+1] = g_nxyz[bk*3+1];
        s_ctr[tid*3+2] = g_nxyz[bk*3+2];
    }
    __syncthreads();

    for (int idx = tid; idx < 128*CIN; idx += 256) {
        int r = idx / CIN, c = idx - r*CIN;
        int nid = s_nid[r];
        int b = (m0 + r) >> 14;
        float v;
        if (c < 3) v = xyz[((size_t)b*NPT + nid)*3 + c] - s_ctr[r*3 + c];
        else       v = points[((size_t)b*NPT + nid)*DD + (c-3)];
        sA[c*SAST + r] = v;
    }
    for (int idx = tid; idx < CIN*CC; idx += 256) sB[idx] = g_W1T[idx];
    __syncthreads();

    const int ty = tid >> 4, tx = tid & 15;
    unsigned long long acc[8][4];
#pragma unroll
    for (int i = 0; i < 8; i++)
#pragma unroll
        for (int j = 0; j < 4; j++) acc[i][j] = 0ull;

#pragma unroll 2
    for (int k = 0; k < CIN; k++) {
        const float* pa = sA + k*SAST + ty*8;
        float4 a0 = *(const float4*)pa;
        float4 a1 = *(const float4*)(pa + 4);
        ulonglong2 b01 = *(const ulonglong2*)(sB + k*CC + tx*8);
        ulonglong2 b23 = *(const ulonglong2*)(sB + k*CC + tx*8 + 4);
        unsigned long long av[8] = {pk2(a0.x,a0.x), pk2(a0.y,a0.y), pk2(a0.z,a0.z), pk2(a0.w,a0.w),
                                    pk2(a1.x,a1.x), pk2(a1.y,a1.y), pk2(a1.z,a1.z), pk2(a1.w,a1.w)};
        unsigned long long bv[4] = {b01.x,b01.y,b23.x,b23.y};
#pragma unroll
        for (int i = 0; i < 8; i++)
#pragma unroll
            for (int j = 0; j < 4; j++) fma2(acc[i][j], av[i], bv[j]);
    }
    float4 q0 = *(const float4*)(bias + tx*8);
    float4 q1 = *(const float4*)(bias + tx*8 + 4);
    float bb[8] = {q0.x,q0.y,q0.z,q0.w,q1.x,q1.y,q1.z,q1.w};
    float s8[8] = {0,0,0,0,0,0,0,0}, sq8[8] = {0,0,0,0,0,0,0,0};
#pragma unroll
    for (int i = 0; i < 8; i++) {
        size_t ro = (size_t)(m0 + ty*8 + i)*CC + tx*8;
        float2 p0 = u2f(acc[i][0]), p1 = u2f(acc[i][1]);
        float2 p2 = u2f(acc[i][2]), p3 = u2f(acc[i][3]);
        float v[8] = {p0.x+bb[0], p0.y+bb[1], p1.x+bb[2], p1.y+bb[3],
                      p2.x+bb[4], p2.y+bb[5], p3.x+bb[6], p3.y+bb[7]};
#pragma unroll
        for (int j = 0; j < 8; j++) { s8[j] += v[j]; sq8[j] = fmaf(v[j], v[j], sq8[j]); }
        *(float4*)(g_h1 + ro)     = make_float4(v[0],v[1],v[2],v[3]);
        *(float4*)(g_h1 + ro + 4) = make_float4(v[4],v[5],v[6],v[7]);
    }
    __syncthreads();
    stats_epilogue(sA, s8, sq8, ty, tx, tid, blockIdx.x);
}

// ---------------- GEMM2 (fused stats) ----------------
__global__ void __launch_bounds__(256, 2) gemm2_kernel(const float* __restrict__ bias) {
    extern __shared__ float sm[];
    float* sA = sm;                           // 64 * SAST
    float* sB = sm + 64*SAST;                 // 64 * 128
    const int m0 = blockIdx.x * 128;
    const int tid = threadIdx.x;
    const int ty = tid >> 4, tx = tid & 15;

    unsigned long long acc[8][4];
#pragma unroll
    for (int i = 0; i < 8; i++)
#pragma unroll
        for (int j = 0; j < 4; j++) acc[i][j] = 0ull;

    for (int kc = 0; kc < CC; kc += 64) {
        __syncthreads();
        for (int idx = tid; idx < 128*64; idx += 256) {
            int r = idx >> 6, c = idx & 63;
            int ch = kc + c;
            float x = g_h1[(size_t)(m0 + r)*CC + ch];
            sA[c*SAST + r] = fmaxf(fmaf(x, g_scale[0][ch], g_shift[0][ch]), 0.0f);
        }
        for (int idx = tid; idx < 64*CC; idx += 256) sB[idx] = g_W2T[kc*CC + idx];
        __syncthreads();

#pragma unroll 2
        for (int k = 0; k < 64; k++) {
            const float* pa = sA + k*SAST + ty*8;
            float4 a0 = *(const float4*)pa;
            float4 a1 = *(const float4*)(pa + 4);
            ulonglong2 b01 = *(const ulonglong2*)(sB + k*CC + tx*8);
            ulonglong2 b23 = *(const ulonglong2*)(sB + k*CC + tx*8 + 4);
            unsigned long long av[8] = {pk2(a0.x,a0.x), pk2(a0.y,a0.y), pk2(a0.z,a0.z), pk2(a0.w,a0.w),
                                        pk2(a1.x,a1.x), pk2(a1.y,a1.y), pk2(a1.z,a1.z), pk2(a1.w,a1.w)};
            unsigned long long bv[4] = {b01.x,b01.y,b23.x,b23.y};
#pragma unroll
            for (int i = 0; i < 8; i++)
#pragma unroll
                for (int j = 0; j < 4; j++) fma2(acc[i][j], av[i], bv[j]);
        }
    }
    float4 q0 = *(const float4*)(bias + tx*8);
    float4 q1 = *(const float4*)(bias + tx*8 + 4);
    float bb[8] = {q0.x,q0.y,q0.z,q0.w,q1.x,q1.y,q1.z,q1.w};
    float s8[8] = {0,0,0,0,0,0,0,0}, sq8[8] = {0,0,0,0,0,0,0,0};
#pragma unroll
    for (int i = 0; i < 8; i++) {
        size_t ro = (size_t)(m0 + ty*8 + i)*CC + tx*8;
        float2 p0 = u2f(acc[i][0]), p1 = u2f(acc[i][1]);
        float2 p2 = u2f(acc[i][2]), p3 = u2f(acc[i][3]);
        float v[8] = {p0.x+bb[0], p0.y+bb[1], p1.x+bb[2], p1.y+bb[3],
                      p2.x+bb[4], p2.y+bb[5], p3.x+bb[6], p3.y+bb[7]};
#pragma unroll
        for (int j = 0; j < 8; j++) { s8[j] += v[j]; sq8[j] = fmaf(v[j], v[j], sq8[j]); }
        *(float4*)(g_h2 + ro)     = make_float4(v[0],v[1],v[2],v[3]);
        *(float4*)(g_h2 + ro + 4) = make_float4(v[4],v[5],v[6],v[7]);
    }
    __syncthreads();
    stats_epilogue(sA, s8, sq8, ty, tx, tid, blockIdx.x);
}

// ---------------- BN finalize ----------------
__global__ void bnfin_kernel(int layer, const float* __restrict__ g,
                             const float* __restrict__ be) {
    int ch = threadIdx.x;
    float s = 0.0f, sq = 0.0f;
#pragma unroll 8
    for (int i = 0; i < 1024; i++) {
        s  += g_part[i*CC + ch];
        sq += g_part[1024*CC + i*CC + ch];
    }
    float inv = 1.0f / (float)MT;
    float mean = s * inv;
    float var  = sq * inv - mean*mean;
    float rs   = rsqrtf(var + EPSBN);
    float sc   = rs * g[ch];
    g_scale[layer][ch] = sc;
    g_shift[layer][ch] = be[ch] - mean*sc;
}

// ---------------- final: relu(bn(h2)) max over NN ----------------
__global__ void final_kernel(float* __restrict__ out, int off) {
    int bk = blockIdx.x;
    int ch = threadIdx.x;
    const float* p = g_h2 + (size_t)bk*NNB*CC + ch;
    float sc = g_scale[1][ch], sh = g_shift[1][ch];
    float m = -3.4e38f;
#pragma unroll
    for (int s = 0; s < NNB; s++)
        m = fmaxf(m, fmaxf(fmaf(p[(size_t)s*CC], sc, sh), 0.0f));
    out[(size_t)off + (size_t)bk*CC + ch] = m;
}

// ---------------- launch ----------------
extern "C" void kernel_launch(void* const* d_in, const int* in_sizes, int n_in,
                              void* d_out, int out_size) {
    const float* xyz    = (const float*)d_in[0];
    const float* points = (const float*)d_in[1];
    const float* W1     = (const float*)d_in[2];
    const float* b1     = (const float*)d_in[3];
    const float* g1     = (const float*)d_in[4];
    const float* be1    = (const float*)d_in[5];
    const float* W2     = (const float*)d_in[6];
    const float* b2     = (const float*)d_in[7];
    const float* g2     = (const float*)d_in[8];
    const float* be2    = (const float*)d_in[9];
    float* out = (float*)d_out;

    const int has_xyz = (out_size >= BB*KP*3 + BB*KP*CC) ? 1 : 0;
    float* outx = has_xyz ? out : nullptr;
    const int poff = has_xyz ? BB*KP*3 : 0;

    const int fps_smem  = 3*NPT*(int)sizeof(float) + 32*(int)sizeof(unsigned long long);
    const int knn_smem  = 4*NPT*(int)sizeof(float);
    const int g1_smem   = (CIN*SAST + CIN*CC)*(int)sizeof(float);
    const int g2_smem   = (64*SAST + 64*CC)*(int)sizeof(float);
    cudaFuncSetAttribute(fps_kernel,  cudaFuncAttributeMaxDynamicSharedMemorySize, fps_smem);
    cudaFuncSetAttribute(knn_kernel,  cudaFuncAttributeMaxDynamicSharedMemorySize, knn_smem);
    cudaFuncSetAttribute(gemm1_kernel,cudaFuncAttributeMaxDynamicSharedMemorySize, g1_smem);
    cudaFuncSetAttribute(gemm2_kernel,cudaFuncAttributeMaxDynamicSharedMemorySize, g2_smem);

    fps_kernel<<<BB, 512, fps_smem>>>(xyz, outx);
    wt_kernel<<<1, 256>>>(W1, W2);
    knn_kernel<<<(BB*KP)/4, 128, knn_smem>>>(xyz);
    gemm1_kernel<<<MT/128, 256, g1_smem>>>(xyz, points, b1);
    bnfin_kernel<<<1, 128>>>(0, g1, be1);
    gemm2_kernel<<<MT/128, 256, g2_smem>>>(b2);
    bnfin_kernel<<<1, 128>>>(1, g2, be2);
    final_kernel<<<BB*KP, 128>>>(out, poff);
}

// round 6
// speedup vs baseline: 1.0137x; 1.0137x over previous
#include <cuda_runtime.h>

#define BB   8
#define NPT  4096
#define DD   64
#define KP   1024
#define NNB  16
#define CC   128
#define CIN  67            // D + 3
#define MT   (BB*KP*NNB)   // 131072 rows
#define EPSBN 1e-5f

// ---------------- scratch ----------------
__device__ float g_h1[(size_t)MT*CC];
__device__ float g_h2[(size_t)MT*CC];
__device__ int   g_knn[MT];
__device__ float g_nxyz[BB*KP*3];
__device__ float g_W1T[CIN*CC];
__device__ float g_W2T[CC*CC];
__device__ float g_part[2*1024*CC];
__device__ float g_scale[2][CC];
__device__ float g_shift[2][CC];

// ---------------- helpers ----------------
__device__ __forceinline__ void fma2(unsigned long long& d, unsigned long long a, unsigned long long b) {
    asm("fma.rn.f32x2 %0,%1,%2,%0;" : "+l"(d) : "l"(a), "l"(b));
}
__device__ __forceinline__ unsigned long long mul2(unsigned long long a, unsigned long long b) {
    unsigned long long r; asm("mul.rn.f32x2 %0,%1,%2;" : "=l"(r) : "l"(a), "l"(b)); return r;
}
__device__ __forceinline__ unsigned long long add2(unsigned long long a, unsigned long long b) {
    unsigned long long r; asm("add.rn.f32x2 %0,%1,%2;" : "=l"(r) : "l"(a), "l"(b)); return r;
}
__device__ __forceinline__ unsigned long long pk2(float lo, float hi) {
    unsigned long long r; asm("mov.b64 %0,{%1,%2};" : "=l"(r) : "f"(lo), "f"(hi)); return r;
}
__device__ __forceinline__ float2 u2f(unsigned long long v) {
    float2 f; asm("mov.b64 {%0,%1},%2;" : "=f"(f.x), "=f"(f.y) : "l"(v)); return f;
}

// ---------------- prelaunch kernels (also align fps to ncu capture slot 5) ----------------
__global__ void wt1_kernel(const float* __restrict__ W1) {
    for (int idx = threadIdx.x; idx < CC*CIN; idx += blockDim.x) {
        int o = idx / CIN, c = idx - o*CIN;
        g_W1T[c*CC + o] = W1[idx];
    }
}
__global__ void wt2_kernel(const float* __restrict__ W2) {
    for (int idx = threadIdx.x; idx < CC*CC; idx += blockDim.x) {
        int o = idx >> 7, c = idx & 127;
        g_W2T[c*CC + o] = W2[idx];
    }
}
__global__ void zz_kernel() {
    g_part[blockIdx.x * blockDim.x + threadIdx.x] = 0.0f;
}

// ---------------- FPS v6: 256 thr/block, 16 pts/thr, half the shuffle traffic ----------------
// Point mapping p = tid*16 + i (monotone in tid,i) => lowest lane/slot = lowest index.
__global__ void fps_kernel(const float* __restrict__ xyz, float* __restrict__ outx) {
    extern __shared__ float fsm[];
    float* sx = fsm;
    float* sy = fsm + NPT;
    float* sz = fsm + 2*NPT;
    unsigned long long* slot = (unsigned long long*)(fsm + 3*NPT);  // [2][8]

    const int b    = blockIdx.x;
    const int tid  = threadIdx.x;            // 256
    const int lane = tid & 31, warp = tid >> 5;  // 8 warps
    const float* base = xyz + (size_t)b*NPT*3;

    // 16 consecutive points = 48 floats = 12 float4
    float c[48];
    {
        const float4* s4 = (const float4*)(base + tid*48);
#pragma unroll
        for (int q = 0; q < 12; q++) {
            float4 v = s4[q];
            c[4*q+0] = v.x; c[4*q+1] = v.y; c[4*q+2] = v.z; c[4*q+3] = v.w;
        }
    }
    unsigned long long pxp[8], pyp[8], pzp[8];
    float dist[16];
#pragma unroll
    for (int q = 0; q < 8; q++) {
        pxp[q] = pk2(c[6*q+0], c[6*q+3]);
        pyp[q] = pk2(c[6*q+1], c[6*q+4]);
        pzp[q] = pk2(c[6*q+2], c[6*q+5]);
        dist[2*q] = 1e10f; dist[2*q+1] = 1e10f;
    }
#pragma unroll
    for (int i = 0; i < 16; i++) {
        int p = tid*16 + i;
        sx[p] = c[3*i+0]; sy[p] = c[3*i+1]; sz[p] = c[3*i+2];
    }
    __syncthreads();

    int far = 0;
    for (int t = 0; t < KP; t++) {
        float cx = sx[far], cy = sy[far], cz = sz[far];
        if (tid == 0) {
            int o = (b*KP + t)*3;
            g_nxyz[o+0] = cx; g_nxyz[o+1] = cy; g_nxyz[o+2] = cz;
            if (outx) { outx[o+0] = cx; outx[o+1] = cy; outx[o+2] = cz; }
        }
        unsigned long long ncx = pk2(-cx, -cx), ncy = pk2(-cy, -cy), ncz = pk2(-cz, -cz);
#pragma unroll
        for (int q = 0; q < 8; q++) {
            unsigned long long dx = add2(pxp[q], ncx);
            unsigned long long dy = add2(pyp[q], ncy);
            unsigned long long dz = add2(pzp[q], ncz);
            unsigned long long dd = mul2(dx, dx);
            fma2(dd, dy, dy);
            fma2(dd, dz, dz);
            float2 e = u2f(dd);
            dist[2*q]   = fminf(dist[2*q],   e.x);
            dist[2*q+1] = fminf(dist[2*q+1], e.y);
        }
        // thread-local max tree (value only)
        float h[8];
#pragma unroll
        for (int i = 0; i < 8; i++) h[i] = fmaxf(dist[2*i], dist[2*i+1]);
        float h0 = fmaxf(fmaxf(h[0], h[1]), fmaxf(h[2], h[3]));
        float h1 = fmaxf(fmaxf(h[4], h[5]), fmaxf(h[6], h[7]));
        float tm = fmaxf(h0, h1);
        // 5-level value-only butterfly
        float m = tm;
#pragma unroll
        for (int o = 16; o > 0; o >>= 1)
            m = fmaxf(m, __shfl_xor_sync(0xffffffffu, m, o));
        // lowest matching slot within thread
        int li = 15;
#pragma unroll
        for (int i = 14; i >= 0; i--) li = (dist[i] == m) ? i : li;
        unsigned g = (unsigned)(tid*16 + li);
        unsigned mask = __ballot_sync(0xffffffffu, tm == m);
        unsigned widx = __shfl_sync(0xffffffffu, g, __ffs(mask) - 1);
        const int par = (t & 1) * 8;
        if (lane == 0)
            slot[par + warp] = ((unsigned long long)__float_as_uint(m) << 32) | widx;
        __syncthreads();
        // phase 2: 8 slots, all warps redundantly
        unsigned long long kk = slot[par + (lane & 7)];
        unsigned val = (unsigned)(kk >> 32), idx = (unsigned)kk;
        unsigned vm = val;
#pragma unroll
        for (int o = 4; o > 0; o >>= 1)
            vm = max(vm, __shfl_xor_sync(0xffffffffu, vm, o));
        unsigned m2 = __ballot_sync(0xffffffffu, val == vm) & 0xFFu;
        if (__popc(m2) > 1) {   // warp-uniform rare path: exact min index over ties
            unsigned cand = (val == vm && lane < 8) ? idx : 0xFFFFFFFFu;
#pragma unroll
            for (int o = 4; o > 0; o >>= 1)
                cand = min(cand, __shfl_xor_sync(0xffffffffu, cand, o));
            far = (int)cand;
        } else {
            far = (int)__shfl_sync(0xffffffffu, idx, __ffs(m2) - 1);
        }
    }
}

// ---------------- kNN: one warp per center ----------------
__global__ void knn_kernel(const float* __restrict__ xyz) {
    extern __shared__ float sm[];
    float* spx = sm;
    float* spy = sm + NPT;
    float* spz = sm + 2*NPT;
    float* sn  = sm + 3*NPT;

    int cid0 = blockIdx.x * 4;
    int b    = cid0 >> 10;
    const float* base = xyz + (size_t)b*NPT*3;
    for (int j = threadIdx.x; j < NPT; j += 128) {
        float x = base[j*3+0], y = base[j*3+1], z = base[j*3+2];
        spx[j] = x; spy[j] = y; spz[j] = z;
        sn[j]  = x*x + y*y + z*z;
    }
    __syncthreads();

    int w = threadIdx.x >> 5, l = threadIdx.x & 31;
    int cid = cid0 + w;
    float cx = g_nxyz[cid*3+0], cy = g_nxyz[cid*3+1], cz = g_nxyz[cid*3+2];
    float cn = cx*cx + cy*cy + cz*cz;

    float bd[16]; int bi[16];
#pragma unroll
    for (int k = 0; k < 16; k++) { bd[k] = 3.4e38f; bi[k] = 1 << 30; }

    for (int j = l; j < NPT; j += 32) {
        float dot = cx*spx[j] + cy*spy[j] + cz*spz[j];
        float sq  = cn + sn[j] - 2.0f*dot;
        if (sq < bd[15] || (sq == bd[15] && j < bi[15])) {
            float d = sq; int ii = j;
#pragma unroll
            for (int k = 0; k < 16; k++) {
                bool sw = (d < bd[k]) || (d == bd[k] && ii < bi[k]);
                float td = bd[k]; int ti = bi[k];
                if (sw) { bd[k] = d; bi[k] = ii; d = td; ii = ti; }
            }
        }
    }
    for (int s = 0; s < 16; s++) {
        float v = bd[0]; int vi = bi[0];
#pragma unroll
        for (int o = 16; o > 0; o >>= 1) {
            float ov = __shfl_xor_sync(0xffffffffu, v, o);
            int   oi = __shfl_xor_sync(0xffffffffu, vi, o);
            if (ov < v || (ov == v && oi < vi)) { v = ov; vi = oi; }
        }
        if (bd[0] == v && bi[0] == vi) {
#pragma unroll
            for (int k = 0; k < 15; k++) { bd[k] = bd[k+1]; bi[k] = bi[k+1]; }
            bd[15] = 3.4e38f; bi[15] = 1 << 30;
        }
        if (l == 0) g_knn[cid*16 + s] = vi;
    }
}

#define SAST 132   // scalar A tile stride (floats)

// stats epilogue: per-block column sum/sumsq -> g_part (reuses sA region)
__device__ __forceinline__ void stats_epilogue(float* red, const float s8[8], const float q8[8],
                                               int ty, int tx, int tid, int blk) {
#pragma unroll
    for (int j = 0; j < 8; j++) {
        red[ty*256 + tx*8 + j]       = s8[j];
        red[ty*256 + 128 + tx*8 + j] = q8[j];
    }
    __syncthreads();
    if (tid < 128) {
        float s = 0.0f, q = 0.0f;
#pragma unroll
        for (int y = 0; y < 16; y++) {
            s += red[y*256 + tid];
            q += red[y*256 + 128 + tid];
        }
        g_part[blk*CC + tid]           = s;
        g_part[1024*CC + blk*CC + tid] = q;
    }
}

// ---------------- GEMM1 (fused gather + stats) ----------------
__global__ void __launch_bounds__(256, 2) gemm1_kernel(const float* __restrict__ xyz,
                             const float* __restrict__ points,
                             const float* __restrict__ bias) {
    extern __shared__ float sm[];
    float* sA = sm;                           // CIN * SAST
    float* sB = sm + CIN*SAST;                // CIN * 128
    __shared__ int   s_nid[128];
    __shared__ float s_ctr[128*3];

    const int m0 = blockIdx.x * 128;
    const int tid = threadIdx.x;              // 256

    if (tid < 128) {
        int gw = m0 + tid;
        s_nid[tid] = g_knn[gw];
        int bk = gw >> 4;
        s_ctr[tid*3+0] = g_nxyz[bk*3+0];
        s_ctr[tid*3+1] = g_nxyz[bk*3+1];
        s_ctr[tid*3+2] = g_nxyz[bk*3+2];
    }
    __syncthreads();

    for (int idx = tid; idx < 128*CIN; idx += 256) {
        int r = idx / CIN, c = idx - r*CIN;
        int nid = s_nid[r];
        int b = (m0 + r) >> 14;
        float v;
        if (c < 3) v = xyz[((size_t)b*NPT + nid)*3 + c] - s_ctr[r*3 + c];
        else       v = points[((size_t)b*NPT + nid)*DD + (c-3)];
        sA[c*SAST + r] = v;
    }
    for (int idx = tid; idx < CIN*CC; idx += 256) sB[idx] = g_W1T[idx];
    __syncthreads();

    const int ty = tid >> 4, tx = tid & 15;
    unsigned long long acc[8][4];
#pragma unroll
    for (int i = 0; i < 8; i++)
#pragma unroll
        for (int j = 0; j < 4; j++) acc[i][j] = 0ull;

#pragma unroll 2
    for (int k = 0; k < CIN; k++) {
        const float* pa = sA + k*SAST + ty*8;
        float4 a0 = *(const float4*)pa;
        float4 a1 = *(const float4*)(pa + 4);
        ulonglong2 b01 = *(const ulonglong2*)(sB + k*CC + tx*8);
        ulonglong2 b23 = *(const ulonglong2*)(sB + k*CC + tx*8 + 4);
        unsigned long long av[8] = {pk2(a0.x,a0.x), pk2(a0.y,a0.y), pk2(a0.z,a0.z), pk2(a0.w,a0.w),
                                    pk2(a1.x,a1.x), pk2(a1.y,a1.y), pk2(a1.z,a1.z), pk2(a1.w,a1.w)};
        unsigned long long bv[4] = {b01.x,b01.y,b23.x,b23.y};
#pragma unroll
        for (int i = 0; i < 8; i++)
#pragma unroll
            for (int j = 0; j < 4; j++) fma2(acc[i][j], av[i], bv[j]);
    }
    float4 q0 = *(const float4*)(bias + tx*8);
    float4 q1 = *(const float4*)(bias + tx*8 + 4);
    float bb[8] = {q0.x,q0.y,q0.z,q0.w,q1.x,q1.y,q1.z,q1.w};
    float s8[8] = {0,0,0,0,0,0,0,0}, sq8[8] = {0,0,0,0,0,0,0,0};
#pragma unroll
    for (int i = 0; i < 8; i++) {
        size_t ro = (size_t)(m0 + ty*8 + i)*CC + tx*8;
        float2 p0 = u2f(acc[i][0]), p1 = u2f(acc[i][1]);
        float2 p2 = u2f(acc[i][2]), p3 = u2f(acc[i][3]);
        float v[8] = {p0.x+bb[0], p0.y+bb[1], p1.x+bb[2], p1.y+bb[3],
                      p2.x+bb[4], p2.y+bb[5], p3.x+bb[6], p3.y+bb[7]};
#pragma unroll
        for (int j = 0; j < 8; j++) { s8[j] += v[j]; sq8[j] = fmaf(v[j], v[j], sq8[j]); }
        *(float4*)(g_h1 + ro)     = make_float4(v[0],v[1],v[2],v[3]);
        *(float4*)(g_h1 + ro + 4) = make_float4(v[4],v[5],v[6],v[7]);
    }
    __syncthreads();
    stats_epilogue(sA, s8, sq8, ty, tx, tid, blockIdx.x);
}

// ---------------- GEMM2 (fused stats) ----------------
__global__ void __launch_bounds__(256, 2) gemm2_kernel(const float* __restrict__ bias) {
    extern __shared__ float sm[];
    float* sA = sm;                           // 64 * SAST
    float* sB = sm + 64*SAST;                 // 64 * 128
    const int m0 = blockIdx.x * 128;
    const int tid = threadIdx.x;
    const int ty = tid >> 4, tx = tid & 15;

    unsigned long long acc[8][4];
#pragma unroll
    for (int i = 0; i < 8; i++)
#pragma unroll
        for (int j = 0; j < 4; j++) acc[i][j] = 0ull;

    for (int kc = 0; kc < CC; kc += 64) {
        __syncthreads();
        for (int idx = tid; idx < 128*64; idx += 256) {
            int r = idx >> 6, c = idx & 63;
            int ch = kc + c;
            float x = g_h1[(size_t)(m0 + r)*CC + ch];
            sA[c*SAST + r] = fmaxf(fmaf(x, g_scale[0][ch], g_shift[0][ch]), 0.0f);
        }
        for (int idx = tid; idx < 64*CC; idx += 256) sB[idx] = g_W2T[kc*CC + idx];
        __syncthreads();

#pragma unroll 2
        for (int k = 0; k < 64; k++) {
            const float* pa = sA + k*SAST + ty*8;
            float4 a0 = *(const float4*)pa;
            float4 a1 = *(const float4*)(pa + 4);
            ulonglong2 b01 = *(const ulonglong2*)(sB + k*CC + tx*8);
            ulonglong2 b23 = *(const ulonglong2*)(sB + k*CC + tx*8 + 4);
            unsigned long long av[8] = {pk2(a0.x,a0.x), pk2(a0.y,a0.y), pk2(a0.z,a0.z), pk2(a0.w,a0.w),
                                        pk2(a1.x,a1.x), pk2(a1.y,a1.y), pk2(a1.z,a1.z), pk2(a1.w,a1.w)};
            unsigned long long bv[4] = {b01.x,b01.y,b23.x,b23.y};
#pragma unroll
            for (int i = 0; i < 8; i++)
#pragma unroll
                for (int j = 0; j < 4; j++) fma2(acc[i][j], av[i], bv[j]);
        }
    }
    float4 q0 = *(const float4*)(bias + tx*8);
    float4 q1 = *(const float4*)(bias + tx*8 + 4);
    float bb[8] = {q0.x,q0.y,q0.z,q0.w,q1.x,q1.y,q1.z,q1.w};
    float s8[8] = {0,0,0,0,0,0,0,0}, sq8[8] = {0,0,0,0,0,0,0,0};
#pragma unroll
    for (int i = 0; i < 8; i++) {
        size_t ro = (size_t)(m0 + ty*8 + i)*CC + tx*8;
        float2 p0 = u2f(acc[i][0]), p1 = u2f(acc[i][1]);
        float2 p2 = u2f(acc[i][2]), p3 = u2f(acc[i][3]);
        float v[8] = {p0.x+bb[0], p0.y+bb[1], p1.x+bb[2], p1.y+bb[3],
                      p2.x+bb[4], p2.y+bb[5], p3.x+bb[6], p3.y+bb[7]};
#pragma unroll
        for (int j = 0; j < 8; j++) { s8[j] += v[j]; sq8[j] = fmaf(v[j], v[j], sq8[j]); }
        *(float4*)(g_h2 + ro)     = make_float4(v[0],v[1],v[2],v[3]);
        *(float4*)(g_h2 + ro + 4) = make_float4(v[4],v[5],v[6],v[7]);
    }
    __syncthreads();
    stats_epilogue(sA, s8, sq8, ty, tx, tid, blockIdx.x);
}

// ---------------- BN finalize ----------------
__global__ void bnfin_kernel(int layer, const float* __restrict__ g,
                             const float* __restrict__ be) {
    int ch = threadIdx.x;
    float s = 0.0f, sq = 0.0f;
#pragma unroll 8
    for (int i = 0; i < 1024; i++) {
        s  += g_part[i*CC + ch];
        sq += g_part[1024*CC + i*CC + ch];
    }
    float inv = 1.0f / (float)MT;
    float mean = s * inv;
    float var  = sq * inv - mean*mean;
    float rs   = rsqrtf(var + EPSBN);
    float sc   = rs * g[ch];
    g_scale[layer][ch] = sc;
    g_shift[layer][ch] = be[ch] - mean*sc;
}

// ---------------- final: relu(bn(h2)) max over NN ----------------
__global__ void final_kernel(float* __restrict__ out, int off) {
    int bk = blockIdx.x;
    int ch = threadIdx.x;
    const float* p = g_h2 + (size_t)bk*NNB*CC + ch;
    float sc = g_scale[1][ch], sh = g_shift[1][ch];
    float m = -3.4e38f;
#pragma unroll
    for (int s = 0; s < NNB; s++)
        m = fmaxf(m, fmaxf(fmaf(p[(size_t)s*CC], sc, sh), 0.0f));
    out[(size_t)off + (size_t)bk*CC + ch] = m;
}

// ---------------- launch ----------------
extern "C" void kernel_launch(void* const* d_in, const int* in_sizes, int n_in,
                              void* d_out, int out_size) {
    const float* xyz    = (const float*)d_in[0];
    const float* points = (const float*)d_in[1];
    const float* W1     = (const float*)d_in[2];
    const float* b1     = (const float*)d_in[3];
    const float* g1     = (const float*)d_in[4];
    const float* be1    = (const float*)d_in[5];
    const float* W2     = (const float*)d_in[6];
    const float* b2     = (const float*)d_in[7];
    const float* g2     = (const float*)d_in[8];
    const float* be2    = (const float*)d_in[9];
    float* out = (float*)d_out;

    const int has_xyz = (out_size >= BB*KP*3 + BB*KP*CC) ? 1 : 0;
    float* outx = has_xyz ? out : nullptr;
    const int poff = has_xyz ? BB*KP*3 : 0;

    const int fps_smem  = 3*NPT*(int)sizeof(float) + 16*(int)sizeof(unsigned long long);
    const int knn_smem  = 4*NPT*(int)sizeof(float);
    const int g1_smem   = (CIN*SAST + CIN*CC)*(int)sizeof(float);
    const int g2_smem   = (64*SAST + 64*CC)*(int)sizeof(float);
    cudaFuncSetAttribute(fps_kernel,  cudaFuncAttributeMaxDynamicSharedMemorySize, fps_smem);
    cudaFuncSetAttribute(knn_kernel,  cudaFuncAttributeMaxDynamicSharedMemorySize, knn_smem);
    cudaFuncSetAttribute(gemm1_kernel,cudaFuncAttributeMaxDynamicSharedMemorySize, g1_smem);
    cudaFuncSetAttribute(gemm2_kernel,cudaFuncAttributeMaxDynamicSharedMemorySize, g2_smem);

    // local launch order: fps must be index 3 so ncu (-s 5, offset 2) captures it
    wt1_kernel<<<1, 256>>>(W1);
    wt2_kernel<<<1, 256>>>(W2);
    zz_kernel<<<64, 256>>>();
    fps_kernel<<<BB, 256, fps_smem>>>(xyz, outx);
    knn_kernel<<<(BB*KP)/4, 128, knn_smem>>>(xyz);
    gemm1_kernel<<<MT/128, 256, g1_smem>>>(xyz, points, b1);
    bnfin_kernel<<<1, 128>>>(0, g1, be1);
    gemm2_kernel<<<MT/128, 256, g2_smem>>>(b2);
    bnfin_kernel<<<1, 128>>>(1, g2, be2);
    final_kernel<<<BB*KP, 128>>>(out, poff);
}

// round 7
// speedup vs baseline: 1.5255x; 1.5048x over previous
#include <cuda_runtime.h>

#define BB   8
#define NPT  4096
#define DD   64
#define KP   1024
#define NNB  16
#define CC   128
#define CIN  67            // D + 3
#define MT   (BB*KP*NNB)   // 131072 rows
#define EPSBN 1e-5f

// ---------------- scratch ----------------
__device__ float g_h1[(size_t)MT*CC];
__device__ float g_h2[(size_t)MT*CC];
__device__ int   g_knn[MT];
__device__ float g_nxyz[BB*KP*3];
__device__ float g_W1T[CIN*CC];
__device__ float g_W2T[CC*CC];
__device__ float g_part[2*1024*CC];
__device__ float g_scale[2][CC];
__device__ float g_shift[2][CC];

// ---------------- helpers ----------------
__device__ __forceinline__ void fma2(unsigned long long& d, unsigned long long a, unsigned long long b) {
    asm("fma.rn.f32x2 %0,%1,%2,%0;" : "+l"(d) : "l"(a), "l"(b));
}
__device__ __forceinline__ unsigned long long mul2(unsigned long long a, unsigned long long b) {
    unsigned long long r; asm("mul.rn.f32x2 %0,%1,%2;" : "=l"(r) : "l"(a), "l"(b)); return r;
}
__device__ __forceinline__ unsigned long long add2(unsigned long long a, unsigned long long b) {
    unsigned long long r; asm("add.rn.f32x2 %0,%1,%2;" : "=l"(r) : "l"(a), "l"(b)); return r;
}
__device__ __forceinline__ unsigned long long pk2(float lo, float hi) {
    unsigned long long r; asm("mov.b64 %0,{%1,%2};" : "=l"(r) : "f"(lo), "f"(hi)); return r;
}
__device__ __forceinline__ float2 u2f(unsigned long long v) {
    float2 f; asm("mov.b64 {%0,%1},%2;" : "=f"(f.x), "=f"(f.y) : "l"(v)); return f;
}

// ---------------- weight pre-transpose ----------------
__global__ void wt1_kernel(const float* __restrict__ W1) {
    for (int idx = threadIdx.x; idx < CC*CIN; idx += blockDim.x) {
        int o = idx / CIN, c = idx - o*CIN;
        g_W1T[c*CC + o] = W1[idx];
    }
}
__global__ void wt2_kernel(const float* __restrict__ W2) {
    for (int idx = threadIdx.x; idx < CC*CC; idx += blockDim.x) {
        int o = idx >> 7, c = idx & 127;
        g_W2T[c*CC + o] = W2[idx];
    }
}

// ---------------- FPS: 256 thr/block, 16 pts/thr ----------------
__global__ void fps_kernel(const float* __restrict__ xyz, float* __restrict__ outx) {
    extern __shared__ float fsm[];
    float* sx = fsm;
    float* sy = fsm + NPT;
    float* sz = fsm + 2*NPT;
    unsigned long long* slot = (unsigned long long*)(fsm + 3*NPT);  // [2][8]

    const int b    = blockIdx.x;
    const int tid  = threadIdx.x;            // 256
    const int lane = tid & 31, warp = tid >> 5;  // 8 warps
    const float* base = xyz + (size_t)b*NPT*3;

    float c[48];
    {
        const float4* s4 = (const float4*)(base + tid*48);
#pragma unroll
        for (int q = 0; q < 12; q++) {
            float4 v = s4[q];
            c[4*q+0] = v.x; c[4*q+1] = v.y; c[4*q+2] = v.z; c[4*q+3] = v.w;
        }
    }
    unsigned long long pxp[8], pyp[8], pzp[8];
    float dist[16];
#pragma unroll
    for (int q = 0; q < 8; q++) {
        pxp[q] = pk2(c[6*q+0], c[6*q+3]);
        pyp[q] = pk2(c[6*q+1], c[6*q+4]);
        pzp[q] = pk2(c[6*q+2], c[6*q+5]);
        dist[2*q] = 1e10f; dist[2*q+1] = 1e10f;
    }
#pragma unroll
    for (int i = 0; i < 16; i++) {
        int p = tid*16 + i;
        sx[p] = c[3*i+0]; sy[p] = c[3*i+1]; sz[p] = c[3*i+2];
    }
    __syncthreads();

    int far = 0;
    for (int t = 0; t < KP; t++) {
        float cx = sx[far], cy = sy[far], cz = sz[far];
        if (tid == 0) {
            int o = (b*KP + t)*3;
            g_nxyz[o+0] = cx; g_nxyz[o+1] = cy; g_nxyz[o+2] = cz;
            if (outx) { outx[o+0] = cx; outx[o+1] = cy; outx[o+2] = cz; }
        }
        unsigned long long ncx = pk2(-cx, -cx), ncy = pk2(-cy, -cy), ncz = pk2(-cz, -cz);
#pragma unroll
        for (int q = 0; q < 8; q++) {
            unsigned long long dx = add2(pxp[q], ncx);
            unsigned long long dy = add2(pyp[q], ncy);
            unsigned long long dz = add2(pzp[q], ncz);
            unsigned long long dd = mul2(dx, dx);
            fma2(dd, dy, dy);
            fma2(dd, dz, dz);
            float2 e = u2f(dd);
            dist[2*q]   = fminf(dist[2*q],   e.x);
            dist[2*q+1] = fminf(dist[2*q+1], e.y);
        }
        float h[8];
#pragma unroll
        for (int i = 0; i < 8; i++) h[i] = fmaxf(dist[2*i], dist[2*i+1]);
        float h0 = fmaxf(fmaxf(h[0], h[1]), fmaxf(h[2], h[3]));
        float h1 = fmaxf(fmaxf(h[4], h[5]), fmaxf(h[6], h[7]));
        float tm = fmaxf(h0, h1);
        float m = tm;
#pragma unroll
        for (int o = 16; o > 0; o >>= 1)
            m = fmaxf(m, __shfl_xor_sync(0xffffffffu, m, o));
        int li = 15;
#pragma unroll
        for (int i = 14; i >= 0; i--) li = (dist[i] == m) ? i : li;
        unsigned g = (unsigned)(tid*16 + li);
        unsigned mask = __ballot_sync(0xffffffffu, tm == m);
        unsigned widx = __shfl_sync(0xffffffffu, g, __ffs(mask) - 1);
        const int par = (t & 1) * 8;
        if (lane == 0)
            slot[par + warp] = ((unsigned long long)__float_as_uint(m) << 32) | (unsigned)(~widx);
        __syncthreads();
        // phase 2: 8 slots, u64-key 3-level butterfly (max dist, min index)
        unsigned long long kk = slot[par + (lane & 7)];
#pragma unroll
        for (int o = 4; o > 0; o >>= 1) {
            unsigned long long ok = __shfl_xor_sync(0xffffffffu, kk, o);
            kk = (ok > kk) ? ok : kk;
        }
        far = (int)(~(unsigned)kk);
    }
}

// ---------------- kNN: warp-shared distributed top-16 (lane k holds k-th best) ----------------
__global__ void knn_kernel(const float* __restrict__ xyz) {
    extern __shared__ float sm[];
    float* spx = sm;
    float* spy = sm + NPT;
    float* spz = sm + 2*NPT;
    float* sn  = sm + 3*NPT;

    int cid0 = blockIdx.x * 4;
    int b    = cid0 >> 10;
    const float* base = xyz + (size_t)b*NPT*3;
    for (int j = threadIdx.x; j < NPT; j += 128) {
        float x = base[j*3+0], y = base[j*3+1], z = base[j*3+2];
        spx[j] = x; spy[j] = y; spz[j] = z;
        sn[j]  = x*x + y*y + z*z;
    }
    __syncthreads();

    int w = threadIdx.x >> 5, l = threadIdx.x & 31;
    int cid = cid0 + w;
    float cx = g_nxyz[cid*3+0], cy = g_nxyz[cid*3+1], cz = g_nxyz[cid*3+2];
    float cn = cx*cx + cy*cy + cz*cz;

    float lv = 3.4e38f; int li = 1 << 30;      // lane l<16: l-th smallest (val,idx)
    float tau = 3.4e38f; int ti = 1 << 30;     // broadcast copy of lane15 key

    for (int k = 0; k < 128; k++) {
        int j = k*32 + l;
        float dot = cx*spx[j] + cy*spy[j] + cz*spz[j];
        float sq  = cn + sn[j] - 2.0f*dot;
        unsigned mask = __ballot_sync(0xffffffffu, (sq < tau) || (sq == tau && j < ti));
        while (mask) {
            int src = __ffs(mask) - 1;
            mask &= mask - 1;
            float cv = __shfl_sync(0xffffffffu, sq, src);
            int   cj = k*32 + src;
            if (cv < tau || (cv == tau && cj < ti)) {    // re-check vs updated tail (uniform)
                bool less = (l < 16) && ((lv < cv) || (lv == cv && li < cj));
                unsigned lm = __ballot_sync(0xffffffffu, less);
                int pos = __popc(lm);
                float pv = __shfl_up_sync(0xffffffffu, lv, 1);
                int   pi = __shfl_up_sync(0xffffffffu, li, 1);
                if (l < 16) {
                    if (l == pos)     { lv = cv; li = cj; }
                    else if (l > pos) { lv = pv; li = pi; }
                }
                tau = __shfl_sync(0xffffffffu, lv, 15);
                ti  = __shfl_sync(0xffffffffu, li, 15);
            }
        }
    }
    if (l < 16) g_knn[cid*16 + l] = li;
}

#define SAST 132   // scalar A tile stride (floats)

// stats epilogue: per-block column sum/sumsq -> g_part (reuses sA region)
__device__ __forceinline__ void stats_epilogue(float* red, const float s8[8], const float q8[8],
                                               int ty, int tx, int tid, int blk) {
#pragma unroll
    for (int j = 0; j < 8; j++) {
        red[ty*256 + tx*8 + j]       = s8[j];
        red[ty*256 + 128 + tx*8 + j] = q8[j];
    }
    __syncthreads();
    if (tid < 128) {
        float s = 0.0f, q = 0.0f;
#pragma unroll
        for (int y = 0; y < 16; y++) {
            s += red[y*256 + tid];
            q += red[y*256 + 128 + tid];
        }
        g_part[blk*CC + tid]           = s;
        g_part[1024*CC + blk*CC + tid] = q;
    }
}

// ---------------- GEMM1 (fused gather + stats) ----------------
__global__ void __launch_bounds__(256, 2) gemm1_kernel(const float* __restrict__ xyz,
                             const float* __restrict__ points,
                             const float* __restrict__ bias) {
    extern __shared__ float sm[];
    float* sA = sm;                           // CIN * SAST
    float* sB = sm + CIN*SAST;                // CIN * 128
    __shared__ int   s_nid[128];
    __shared__ float s_ctr[128*3];

    const int m0 = blockIdx.x * 128;
    const int tid = threadIdx.x;              // 256

    if (tid < 128) {
        int gw = m0 + tid;
        s_nid[tid] = g_knn[gw];
        int bk = gw >> 4;
        s_ctr[tid*3+0] = g_nxyz[bk*3+0];
        s_ctr[tid*3+1] = g_nxyz[bk*3+1];
        s_ctr[tid*3+2] = g_nxyz[bk*3+2];
    }
    __syncthreads();

    for (int idx = tid; idx < 128*CIN; idx += 256) {
        int r = idx / CIN, c = idx - r*CIN;
        int nid = s_nid[r];
        int b = (m0 + r) >> 14;
        float v;
        if (c < 3) v = xyz[((size_t)b*NPT + nid)*3 + c] - s_ctr[r*3 + c];
        else       v = points[((size_t)b*NPT + nid)*DD + (c-3)];
        sA[c*SAST + r] = v;
    }
    for (int idx = tid; idx < CIN*CC; idx += 256) sB[idx] = g_W1T[idx];
    __syncthreads();

    const int ty = tid >> 4, tx = tid & 15;
    unsigned long long acc[8][4];
#pragma unroll
    for (int i = 0; i < 8; i++)
#pragma unroll
        for (int j = 0; j < 4; j++) acc[i][j] = 0ull;

#pragma unroll 2
    for (int k = 0; k < CIN; k++) {
        const float* pa = sA + k*SAST + ty*8;
        float4 a0 = *(const float4*)pa;
        float4 a1 = *(const float4*)(pa + 4);
        ulonglong2 b01 = *(const ulonglong2*)(sB + k*CC + tx*8);
        ulonglong2 b23 = *(const ulonglong2*)(sB + k*CC + tx*8 + 4);
        unsigned long long av[8] = {pk2(a0.x,a0.x), pk2(a0.y,a0.y), pk2(a0.z,a0.z), pk2(a0.w,a0.w),
                                    pk2(a1.x,a1.x), pk2(a1.y,a1.y), pk2(a1.z,a1.z), pk2(a1.w,a1.w)};
        unsigned long long bv[4] = {b01.x,b01.y,b23.x,b23.y};
#pragma unroll
        for (int i = 0; i < 8; i++)
#pragma unroll
            for (int j = 0; j < 4; j++) fma2(acc[i][j], av[i], bv[j]);
    }
    float4 q0 = *(const float4*)(bias + tx*8);
    float4 q1 = *(const float4*)(bias + tx*8 + 4);
    float bb[8] = {q0.x,q0.y,q0.z,q0.w,q1.x,q1.y,q1.z,q1.w};
    float s8[8] = {0,0,0,0,0,0,0,0}, sq8[8] = {0,0,0,0,0,0,0,0};
#pragma unroll
    for (int i = 0; i < 8; i++) {
        size_t ro = (size_t)(m0 + ty*8 + i)*CC + tx*8;
        float2 p0 = u2f(acc[i][0]), p1 = u2f(acc[i][1]);
        float2 p2 = u2f(acc[i][2]), p3 = u2f(acc[i][3]);
        float v[8] = {p0.x+bb[0], p0.y+bb[1], p1.x+bb[2], p1.y+bb[3],
                      p2.x+bb[4], p2.y+bb[5], p3.x+bb[6], p3.y+bb[7]};
#pragma unroll
        for (int j = 0; j < 8; j++) { s8[j] += v[j]; sq8[j] = fmaf(v[j], v[j], sq8[j]); }
        *(float4*)(g_h1 + ro)     = make_float4(v[0],v[1],v[2],v[3]);
        *(float4*)(g_h1 + ro + 4) = make_float4(v[4],v[5],v[6],v[7]);
    }
    __syncthreads();
    stats_epilogue(sA, s8, sq8, ty, tx, tid, blockIdx.x);
}

// ---------------- GEMM2 (fused stats) ----------------
__global__ void __launch_bounds__(256, 2) gemm2_kernel(const float* __restrict__ bias) {
    extern __shared__ float sm[];
    float* sA = sm;                           // 64 * SAST
    float* sB = sm + 64*SAST;                 // 64 * 128
    const int m0 = blockIdx.x * 128;
    const int tid = threadIdx.x;
    const int ty = tid >> 4, tx = tid & 15;

    unsigned long long acc[8][4];
#pragma unroll
    for (int i = 0; i < 8; i++)
#pragma unroll
        for (int j = 0; j < 4; j++) acc[i][j] = 0ull;

    for (int kc = 0; kc < CC; kc += 64) {
        __syncthreads();
        for (int idx = tid; idx < 128*64; idx += 256) {
            int r = idx >> 6, c = idx & 63;
            int ch = kc + c;
            float x = g_h1[(size_t)(m0 + r)*CC + ch];
            sA[c*SAST + r] = fmaxf(fmaf(x, g_scale[0][ch], g_shift[0][ch]), 0.0f);
        }
        for (int idx = tid; idx < 64*CC; idx += 256) sB[idx] = g_W2T[kc*CC + idx];
        __syncthreads();

#pragma unroll 2
        for (int k = 0; k < 64; k++) {
            const float* pa = sA + k*SAST + ty*8;
            float4 a0 = *(const float4*)pa;
            float4 a1 = *(const float4*)(pa + 4);
            ulonglong2 b01 = *(const ulonglong2*)(sB + k*CC + tx*8);
            ulonglong2 b23 = *(const ulonglong2*)(sB + k*CC + tx*8 + 4);
            unsigned long long av[8] = {pk2(a0.x,a0.x), pk2(a0.y,a0.y), pk2(a0.z,a0.z), pk2(a0.w,a0.w),
                                        pk2(a1.x,a1.x), pk2(a1.y,a1.y), pk2(a1.z,a1.z), pk2(a1.w,a1.w)};
            unsigned long long bv[4] = {b01.x,b01.y,b23.x,b23.y};
#pragma unroll
            for (int i = 0; i < 8; i++)
#pragma unroll
                for (int j = 0; j < 4; j++) fma2(acc[i][j], av[i], bv[j]);
        }
    }
    float4 q0 = *(const float4*)(bias + tx*8);
    float4 q1 = *(const float4*)(bias + tx*8 + 4);
    float bb[8] = {q0.x,q0.y,q0.z,q0.w,q1.x,q1.y,q1.z,q1.w};
    float s8[8] = {0,0,0,0,0,0,0,0}, sq8[8] = {0,0,0,0,0,0,0,0};
#pragma unroll
    for (int i = 0; i < 8; i++) {
        size_t ro = (size_t)(m0 + ty*8 + i)*CC + tx*8;
        float2 p0 = u2f(acc[i][0]), p1 = u2f(acc[i][1]);
        float2 p2 = u2f(acc[i][2]), p3 = u2f(acc[i][3]);
        float v[8] = {p0.x+bb[0], p0.y+bb[1], p1.x+bb[2], p1.y+bb[3],
                      p2.x+bb[4], p2.y+bb[5], p3.x+bb[6], p3.y+bb[7]};
#pragma unroll
        for (int j = 0; j < 8; j++) { s8[j] += v[j]; sq8[j] = fmaf(v[j], v[j], sq8[j]); }
        *(float4*)(g_h2 + ro)     = make_float4(v[0],v[1],v[2],v[3]);
        *(float4*)(g_h2 + ro + 4) = make_float4(v[4],v[5],v[6],v[7]);
    }
    __syncthreads();
    stats_epilogue(sA, s8, sq8, ty, tx, tid, blockIdx.x);
}

// ---------------- BN finalize: 128 blocks (one per channel), deterministic tree ----------------
__global__ void bnfin_kernel(int layer, const float* __restrict__ g,
                             const float* __restrict__ be) {
    __shared__ float ss[256], qq[256];
    const int ch = blockIdx.x, tid = threadIdx.x;   // 256 threads
    float s = 0.0f, q = 0.0f;
#pragma unroll
    for (int k = 0; k < 4; k++) {
        int i = tid*4 + k;
        s += g_part[i*CC + ch];
        q += g_part[1024*CC + i*CC + ch];
    }
    ss[tid] = s; qq[tid] = q;
    __syncthreads();
    for (int off = 128; off > 0; off >>= 1) {
        if (tid < off) { ss[tid] += ss[tid+off]; qq[tid] += qq[tid+off]; }
        __syncthreads();
    }
    if (tid == 0) {
        float inv = 1.0f / (float)MT;
        float mean = ss[0] * inv;
        float var  = qq[0] * inv - mean*mean;
        float rs   = rsqrtf(var + EPSBN);
        float sc   = rs * g[ch];
        g_scale[layer][ch] = sc;
        g_shift[layer][ch] = be[ch] - mean*sc;
    }
}

// ---------------- final: relu(bn(h2)) max over NN ----------------
__global__ void final_kernel(float* __restrict__ out, int off) {
    int bk = blockIdx.x;
    int ch = threadIdx.x;
    const float* p = g_h2 + (size_t)bk*NNB*CC + ch;
    float sc = g_scale[1][ch], sh = g_shift[1][ch];
    float m = -3.4e38f;
#pragma unroll
    for (int s = 0; s < NNB; s++)
        m = fmaxf(m, fmaxf(fmaf(p[(size_t)s*CC], sc, sh), 0.0f));
    out[(size_t)off + (size_t)bk*CC + ch] = m;
}

// ---------------- launch ----------------
extern "C" void kernel_launch(void* const* d_in, const int* in_sizes, int n_in,
                              void* d_out, int out_size) {
    const float* xyz    = (const float*)d_in[0];
    const float* points = (const float*)d_in[1];
    const float* W1     = (const float*)d_in[2];
    const float* b1     = (const float*)d_in[3];
    const float* g1     = (const float*)d_in[4];
    const float* be1    = (const float*)d_in[5];
    const float* W2     = (const float*)d_in[6];
    const float* b2     = (const float*)d_in[7];
    const float* g2     = (const float*)d_in[8];
    const float* be2    = (const float*)d_in[9];
    float* out = (float*)d_out;

    const int has_xyz = (out_size >= BB*KP*3 + BB*KP*CC) ? 1 : 0;
    float* outx = has_xyz ? out : nullptr;
    const int poff = has_xyz ? BB*KP*3 : 0;

    const int fps_smem  = 3*NPT*(int)sizeof(float) + 16*(int)sizeof(unsigned long long);
    const int knn_smem  = 4*NPT*(int)sizeof(float);
    const int g1_smem   = (CIN*SAST + CIN*CC)*(int)sizeof(float);
    const int g2_smem   = (64*SAST + 64*CC)*(int)sizeof(float);
    cudaFuncSetAttribute(fps_kernel,  cudaFuncAttributeMaxDynamicSharedMemorySize, fps_smem);
    cudaFuncSetAttribute(knn_kernel,  cudaFuncAttributeMaxDynamicSharedMemorySize, knn_smem);
    cudaFuncSetAttribute(gemm1_kernel,cudaFuncAttributeMaxDynamicSharedMemorySize, g1_smem);
    cudaFuncSetAttribute(gemm2_kernel,cudaFuncAttributeMaxDynamicSharedMemorySize, g2_smem);

    // local order: knn at slot 3 -> ncu global slot 5 captures knn this round
    wt1_kernel<<<1, 256>>>(W1);
    wt2_kernel<<<1, 256>>>(W2);
    fps_kernel<<<BB, 256, fps_smem>>>(xyz, outx);
    knn_kernel<<<(BB*KP)/4, 128, knn_smem>>>(xyz);
    gemm1_kernel<<<MT/128, 256, g1_smem>>>(xyz, points, b1);
    bnfin_kernel<<<CC, 256>>>(0, g1, be1);
    gemm2_kernel<<<MT/128, 256, g2_smem>>>(b2);
    bnfin_kernel<<<CC, 256>>>(1, g2, be2);
    final_kernel<<<BB*KP, 128>>>(out, poff);
}

// round 8
// speedup vs baseline: 1.7442x; 1.1433x over previous
#include <cuda_runtime.h>

#define BB   8
#define NPT  4096
#define DD   64
#define KP   1024
#define NNB  16
#define CC   128
#define CIN  67            // D + 3
#define MT   (BB*KP*NNB)   // 131072 rows
#define EPSBN 1e-5f

// ---------------- scratch ----------------
__device__ float g_h1[(size_t)MT*CC];
__device__ float g_h2[(size_t)MT*CC];
__device__ int   g_knn[MT];
__device__ float g_nxyz[BB*KP*3];
__device__ float g_W1T[CIN*CC];
__device__ float g_W2T[CC*CC];
__device__ float g_part[2*1024*CC];
__device__ float g_scale[2][CC];
__device__ float g_shift[2][CC];

// ---------------- helpers ----------------
__device__ __forceinline__ unsigned redux_max_u32(unsigned v) {
    unsigned r; asm("redux.sync.max.u32 %0,%1,0xffffffff;" : "=r"(r) : "r"(v)); return r;
}
__device__ __forceinline__ void fma2(unsigned long long& d, unsigned long long a, unsigned long long b) {
    asm("fma.rn.f32x2 %0,%1,%2,%0;" : "+l"(d) : "l"(a), "l"(b));
}
__device__ __forceinline__ unsigned long long mul2(unsigned long long a, unsigned long long b) {
    unsigned long long r; asm("mul.rn.f32x2 %0,%1,%2;" : "=l"(r) : "l"(a), "l"(b)); return r;
}
__device__ __forceinline__ unsigned long long add2(unsigned long long a, unsigned long long b) {
    unsigned long long r; asm("add.rn.f32x2 %0,%1,%2;" : "=l"(r) : "l"(a), "l"(b)); return r;
}
__device__ __forceinline__ unsigned long long pk2(float lo, float hi) {
    unsigned long long r; asm("mov.b64 %0,{%1,%2};" : "=l"(r) : "f"(lo), "f"(hi)); return r;
}
__device__ __forceinline__ float2 u2f(unsigned long long v) {
    float2 f; asm("mov.b64 {%0,%1},%2;" : "=f"(f.x), "=f"(f.y) : "l"(v)); return f;
}

// ---------------- pre-kernels ----------------
__global__ void wt1_kernel(const float* __restrict__ W1) {
    for (int idx = threadIdx.x; idx < CC*CIN; idx += blockDim.x) {
        int o = idx / CIN, c = idx - o*CIN;
        g_W1T[c*CC + o] = W1[idx];
    }
}
__global__ void wt2_kernel(const float* __restrict__ W2) {
    for (int idx = threadIdx.x; idx < CC*CC; idx += blockDim.x) {
        int o = idx >> 7, c = idx & 127;
        g_W2T[c*CC + o] = W2[idx];
    }
}
__global__ void zz_kernel() {   // keeps fps at ncu capture slot; zeroes g_part (harmless)
    g_part[blockIdx.x * blockDim.x + threadIdx.x] = 0.0f;
}

// ---------------- FPS: 256 thr/block, redux phase-1, u64 butterfly phase-2 ----------------
__global__ void fps_kernel(const float* __restrict__ xyz, float* __restrict__ outx) {
    extern __shared__ float fsm[];
    float* sx = fsm;
    float* sy = fsm + NPT;
    float* sz = fsm + 2*NPT;
    unsigned long long* slot = (unsigned long long*)(fsm + 3*NPT);  // [2][8]

    const int b    = blockIdx.x;
    const int tid  = threadIdx.x;                // 256
    const int lane = tid & 31, warp = tid >> 5;  // 8 warps
    const float* base = xyz + (size_t)b*NPT*3;

    float c[48];
    {
        const float4* s4 = (const float4*)(base + tid*48);
#pragma unroll
        for (int q = 0; q < 12; q++) {
            float4 v = s4[q];
            c[4*q+0] = v.x; c[4*q+1] = v.y; c[4*q+2] = v.z; c[4*q+3] = v.w;
        }
    }
    unsigned long long pxp[8], pyp[8], pzp[8];
    float dist[16];
#pragma unroll
    for (int q = 0; q < 8; q++) {
        pxp[q] = pk2(c[6*q+0], c[6*q+3]);
        pyp[q] = pk2(c[6*q+1], c[6*q+4]);
        pzp[q] = pk2(c[6*q+2], c[6*q+5]);
        dist[2*q] = 1e10f; dist[2*q+1] = 1e10f;
    }
#pragma unroll
    for (int i = 0; i < 16; i++) {
        int p = tid*16 + i;
        sx[p] = c[3*i+0]; sy[p] = c[3*i+1]; sz[p] = c[3*i+2];
    }
    __syncthreads();

    int far = 0;
    for (int t = 0; t < KP; t++) {
        float cx = sx[far], cy = sy[far], cz = sz[far];
        if (tid == 0) {
            int o = (b*KP + t)*3;
            g_nxyz[o+0] = cx; g_nxyz[o+1] = cy; g_nxyz[o+2] = cz;
            if (outx) { outx[o+0] = cx; outx[o+1] = cy; outx[o+2] = cz; }
        }
        unsigned long long ncx = pk2(-cx, -cx), ncy = pk2(-cy, -cy), ncz = pk2(-cz, -cz);
#pragma unroll
        for (int q = 0; q < 8; q++) {
            unsigned long long dx = add2(pxp[q], ncx);
            unsigned long long dy = add2(pyp[q], ncy);
            unsigned long long dz = add2(pzp[q], ncz);
            unsigned long long dd = mul2(dx, dx);
            fma2(dd, dy, dy);
            fma2(dd, dz, dz);
            float2 e = u2f(dd);
            dist[2*q]   = fminf(dist[2*q],   e.x);
            dist[2*q+1] = fminf(dist[2*q+1], e.y);
        }
        float h[8];
#pragma unroll
        for (int i = 0; i < 8; i++) h[i] = fmaxf(dist[2*i], dist[2*i+1]);
        float h0 = fmaxf(fmaxf(h[0], h[1]), fmaxf(h[2], h[3]));
        float h1 = fmaxf(fmaxf(h[4], h[5]), fmaxf(h[6], h[7]));
        float tm = fmaxf(h0, h1);
        // warp max value via single redux (exact: dists are non-negative floats)
        float m = __uint_as_float(redux_max_u32(__float_as_uint(tm)));
        int li = 15;
#pragma unroll
        for (int i = 14; i >= 0; i--) li = (dist[i] == m) ? i : li;
        unsigned g = (unsigned)(tid*16 + li);
        unsigned mask = __ballot_sync(0xffffffffu, tm == m);
        unsigned widx = __shfl_sync(0xffffffffu, g, __ffs(mask) - 1);
        const int par = (t & 1) * 8;
        if (lane == 0)
            slot[par + warp] = ((unsigned long long)__float_as_uint(m) << 32) | (unsigned)(~widx);
        __syncthreads();
        unsigned long long kk = slot[par + (lane & 7)];
#pragma unroll
        for (int o = 4; o > 0; o >>= 1) {
            unsigned long long ok = __shfl_xor_sync(0xffffffffu, kk, o);
            kk = (ok > kk) ? ok : kk;
        }
        far = (int)(~(unsigned)kk);
    }
}

// ---------------- kNN: 8 warps/block, warp-distributed top-16 ----------------
__global__ void knn_kernel(const float* __restrict__ xyz) {
    extern __shared__ float sm[];
    float* spx = sm;
    float* spy = sm + NPT;
    float* spz = sm + 2*NPT;
    float* sn  = sm + 3*NPT;

    int cid0 = blockIdx.x * 8;                 // 1024 blocks
    int b    = cid0 >> 10;
    const float* base = xyz + (size_t)b*NPT*3;
    for (int j = threadIdx.x; j < NPT; j += 256) {
        float x = base[j*3+0], y = base[j*3+1], z = base[j*3+2];
        spx[j] = x; spy[j] = y; spz[j] = z;
        sn[j]  = x*x + y*y + z*z;
    }
    __syncthreads();

    int w = threadIdx.x >> 5, l = threadIdx.x & 31;
    int cid = cid0 + w;
    float cx = g_nxyz[cid*3+0], cy = g_nxyz[cid*3+1], cz = g_nxyz[cid*3+2];
    float cn = cx*cx + cy*cy + cz*cz;

    float lv = 3.4e38f; int li = 1 << 30;
    float tau = 3.4e38f; int ti = 1 << 30;

    for (int k = 0; k < 128; k++) {
        int j = k*32 + l;
        float dot = cx*spx[j] + cy*spy[j] + cz*spz[j];
        float sq  = cn + sn[j] - 2.0f*dot;
        unsigned mask = __ballot_sync(0xffffffffu, (sq < tau) || (sq == tau && j < ti));
        while (mask) {
            int src = __ffs(mask) - 1;
            mask &= mask - 1;
            float cv = __shfl_sync(0xffffffffu, sq, src);
            int   cj = k*32 + src;
            if (cv < tau || (cv == tau && cj < ti)) {
                bool less = (l < 16) && ((lv < cv) || (lv == cv && li < cj));
                unsigned lm = __ballot_sync(0xffffffffu, less);
                int pos = __popc(lm);
                float pv = __shfl_up_sync(0xffffffffu, lv, 1);
                int   pi = __shfl_up_sync(0xffffffffu, li, 1);
                if (l < 16) {
                    if (l == pos)     { lv = cv; li = cj; }
                    else if (l > pos) { lv = pv; li = pi; }
                }
                tau = __shfl_sync(0xffffffffu, lv, 15);
                ti  = __shfl_sync(0xffffffffu, li, 15);
            }
        }
    }
    if (l < 16) g_knn[cid*16 + l] = li;
}

#define SAST 132   // scalar A tile stride (floats)

// software-pipelined fragment MM: prefetch k+1 while computing k
template<int KK>
__device__ __forceinline__ void mm_tile(const float* __restrict__ sA, const float* __restrict__ sB,
                                        int ty, int tx, unsigned long long acc[8][4]) {
    const float* pa = sA + ty*8;
    const float* pb = sB + tx*8;
    float4 ca0 = *(const float4*)pa;
    float4 ca1 = *(const float4*)(pa + 4);
    ulonglong2 cb01 = *(const ulonglong2*)pb;
    ulonglong2 cb23 = *(const ulonglong2*)(pb + 4);
#pragma unroll 2
    for (int k = 0; k < KK; k++) {
        float4 na0, na1; ulonglong2 nb01, nb23;
        if (k + 1 < KK) {
            const float* qa = sA + (k+1)*SAST + ty*8;
            const float* qb = sB + (k+1)*CC + tx*8;
            na0  = *(const float4*)qa;
            na1  = *(const float4*)(qa + 4);
            nb01 = *(const ulonglong2*)qb;
            nb23 = *(const ulonglong2*)(qb + 4);
        }
        unsigned long long av[8] = {pk2(ca0.x,ca0.x), pk2(ca0.y,ca0.y), pk2(ca0.z,ca0.z), pk2(ca0.w,ca0.w),
                                    pk2(ca1.x,ca1.x), pk2(ca1.y,ca1.y), pk2(ca1.z,ca1.z), pk2(ca1.w,ca1.w)};
        unsigned long long bv[4] = {cb01.x, cb01.y, cb23.x, cb23.y};
#pragma unroll
        for (int i = 0; i < 8; i++)
#pragma unroll
            for (int j = 0; j < 4; j++) fma2(acc[i][j], av[i], bv[j]);
        ca0 = na0; ca1 = na1; cb01 = nb01; cb23 = nb23;
    }
}

// stats epilogue: per-block column sum/sumsq -> g_part (reuses sA region)
__device__ __forceinline__ void stats_epilogue(float* red, const float s8[8], const float q8[8],
                                               int ty, int tx, int tid, int blk) {
#pragma unroll
    for (int j = 0; j < 8; j++) {
        red[ty*256 + tx*8 + j]       = s8[j];
        red[ty*256 + 128 + tx*8 + j] = q8[j];
    }
    __syncthreads();
    if (tid < 128) {
        float s = 0.0f, q = 0.0f;
#pragma unroll
        for (int y = 0; y < 16; y++) {
            s += red[y*256 + tid];
            q += red[y*256 + 128 + tid];
        }
        g_part[blk*CC + tid]           = s;
        g_part[1024*CC + blk*CC + tid] = q;
    }
}

// ---------------- GEMM1 (fused gather + stats) ----------------
__global__ void __launch_bounds__(256, 2) gemm1_kernel(const float* __restrict__ xyz,
                             const float* __restrict__ points,
                             const float* __restrict__ bias) {
    extern __shared__ float sm[];
    float* sA = sm;                           // CIN * SAST
    float* sB = sm + CIN*SAST;                // CIN * 128
    __shared__ int   s_nid[128];
    __shared__ float s_ctr[128*3];

    const int m0 = blockIdx.x * 128;
    const int tid = threadIdx.x;              // 256

    if (tid < 128) {
        int gw = m0 + tid;
        s_nid[tid] = g_knn[gw];
        int bk = gw >> 4;
        s_ctr[tid*3+0] = g_nxyz[bk*3+0];
        s_ctr[tid*3+1] = g_nxyz[bk*3+1];
        s_ctr[tid*3+2] = g_nxyz[bk*3+2];
    }
    __syncthreads();

    for (int idx = tid; idx < 128*CIN; idx += 256) {
        int r = idx / CIN, c = idx - r*CIN;
        int nid = s_nid[r];
        int b = (m0 + r) >> 14;
        float v;
        if (c < 3) v = xyz[((size_t)b*NPT + nid)*3 + c] - s_ctr[r*3 + c];
        else       v = points[((size_t)b*NPT + nid)*DD + (c-3)];
        sA[c*SAST + r] = v;
    }
    for (int idx = tid; idx < CIN*CC; idx += 256) sB[idx] = g_W1T[idx];
    __syncthreads();

    const int ty = tid >> 4, tx = tid & 15;
    unsigned long long acc[8][4];
#pragma unroll
    for (int i = 0; i < 8; i++)
#pragma unroll
        for (int j = 0; j < 4; j++) acc[i][j] = 0ull;

    mm_tile<CIN>(sA, sB, ty, tx, acc);

    float4 q0 = *(const float4*)(bias + tx*8);
    float4 q1 = *(const float4*)(bias + tx*8 + 4);
    float bb[8] = {q0.x,q0.y,q0.z,q0.w,q1.x,q1.y,q1.z,q1.w};
    float s8[8] = {0,0,0,0,0,0,0,0}, sq8[8] = {0,0,0,0,0,0,0,0};
#pragma unroll
    for (int i = 0; i < 8; i++) {
        size_t ro = (size_t)(m0 + ty*8 + i)*CC + tx*8;
        float2 p0 = u2f(acc[i][0]), p1 = u2f(acc[i][1]);
        float2 p2 = u2f(acc[i][2]), p3 = u2f(acc[i][3]);
        float v[8] = {p0.x+bb[0], p0.y+bb[1], p1.x+bb[2], p1.y+bb[3],
                      p2.x+bb[4], p2.y+bb[5], p3.x+bb[6], p3.y+bb[7]};
#pragma unroll
        for (int j = 0; j < 8; j++) { s8[j] += v[j]; sq8[j] = fmaf(v[j], v[j], sq8[j]); }
        *(float4*)(g_h1 + ro)     = make_float4(v[0],v[1],v[2],v[3]);
        *(float4*)(g_h1 + ro + 4) = make_float4(v[4],v[5],v[6],v[7]);
    }
    __syncthreads();
    stats_epilogue(sA, s8, sq8, ty, tx, tid, blockIdx.x);
}

// ---------------- GEMM2 (fused stats) ----------------
__global__ void __launch_bounds__(256, 2) gemm2_kernel(const float* __restrict__ bias) {
    extern __shared__ float sm[];
    float* sA = sm;                           // 64 * SAST
    float* sB = sm + 64*SAST;                 // 64 * 128
    const int m0 = blockIdx.x * 128;
    const int tid = threadIdx.x;
    const int ty = tid >> 4, tx = tid & 15;

    unsigned long long acc[8][4];
#pragma unroll
    for (int i = 0; i < 8; i++)
#pragma unroll
        for (int j = 0; j < 4; j++) acc[i][j] = 0ull;

    for (int kc = 0; kc < CC; kc += 64) {
        __syncthreads();
        for (int idx = tid; idx < 128*64; idx += 256) {
            int r = idx >> 6, c = idx & 63;
            int ch = kc + c;
            float x = g_h1[(size_t)(m0 + r)*CC + ch];
            sA[c*SAST + r] = fmaxf(fmaf(x, g_scale[0][ch], g_shift[0][ch]), 0.0f);
        }
        for (int idx = tid; idx < 64*CC; idx += 256) sB[idx] = g_W2T[kc*CC + idx];
        __syncthreads();

        mm_tile<64>(sA, sB, ty, tx, acc);
    }
    float4 q0 = *(const float4*)(bias + tx*8);
    float4 q1 = *(const float4*)(bias + tx*8 + 4);
    float bb[8] = {q0.x,q0.y,q0.z,q0.w,q1.x,q1.y,q1.z,q1.w};
    float s8[8] = {0,0,0,0,0,0,0,0}, sq8[8] = {0,0,0,0,0,0,0,0};
#pragma unroll
    for (int i = 0; i < 8; i++) {
        size_t ro = (size_t)(m0 + ty*8 + i)*CC + tx*8;
        float2 p0 = u2f(acc[i][0]), p1 = u2f(acc[i][1]);
        float2 p2 = u2f(acc[i][2]), p3 = u2f(acc[i][3]);
        float v[8] = {p0.x+bb[0], p0.y+bb[1], p1.x+bb[2], p1.y+bb[3],
                      p2.x+bb[4], p2.y+bb[5], p3.x+bb[6], p3.y+bb[7]};
#pragma unroll
        for (int j = 0; j < 8; j++) { s8[j] += v[j]; sq8[j] = fmaf(v[j], v[j], sq8[j]); }
        *(float4*)(g_h2 + ro)     = make_float4(v[0],v[1],v[2],v[3]);
        *(float4*)(g_h2 + ro + 4) = make_float4(v[4],v[5],v[6],v[7]);
    }
    __syncthreads();
    stats_epilogue(sA, s8, sq8, ty, tx, tid, blockIdx.x);
}

// ---------------- BN finalize: 128 blocks, deterministic tree ----------------
__global__ void bnfin_kernel(int layer, const float* __restrict__ g,
                             const float* __restrict__ be) {
    __shared__ float ss[256], qq[256];
    const int ch = blockIdx.x, tid = threadIdx.x;   // 256 threads
    float s = 0.0f, q = 0.0f;
#pragma unroll
    for (int k = 0; k < 4; k++) {
        int i = tid*4 + k;
        s += g_part[i*CC + ch];
        q += g_part[1024*CC + i*CC + ch];
    }
    ss[tid] = s; qq[tid] = q;
    __syncthreads();
    for (int off = 128; off > 0; off >>= 1) {
        if (tid < off) { ss[tid] += ss[tid+off]; qq[tid] += qq[tid+off]; }
        __syncthreads();
    }
    if (tid == 0) {
        float inv = 1.0f / (float)MT;
        float mean = ss[0] * inv;
        float var  = qq[0] * inv - mean*mean;
        float rs   = rsqrtf(var + EPSBN);
        float sc   = rs * g[ch];
        g_scale[layer][ch] = sc;
        g_shift[layer][ch] = be[ch] - mean*sc;
    }
}

// ---------------- final: relu(bn(h2)) max over NN ----------------
__global__ void final_kernel(float* __restrict__ out, int off) {
    int bk = blockIdx.x;
    int ch = threadIdx.x;
    const float* p = g_h2 + (size_t)bk*NNB*CC + ch;
    float sc = g_scale[1][ch], sh = g_shift[1][ch];
    float m = -3.4e38f;
#pragma unroll
    for (int s = 0; s < NNB; s++)
        m = fmaxf(m, fmaxf(fmaf(p[(size_t)s*CC], sc, sh), 0.0f));
    out[(size_t)off + (size_t)bk*CC + ch] = m;
}

// ---------------- launch ----------------
extern "C" void kernel_launch(void* const* d_in, const int* in_sizes, int n_in,
                              void* d_out, int out_size) {
    const float* xyz    = (const float*)d_in[0];
    const float* points = (const float*)d_in[1];
    const float* W1     = (const float*)d_in[2];
    const float* b1     = (const float*)d_in[3];
    const float* g1     = (const float*)d_in[4];
    const float* be1    = (const float*)d_in[5];
    const float* W2     = (const float*)d_in[6];
    const float* b2     = (const float*)d_in[7];
    const float* g2     = (const float*)d_in[8];
    const float* be2    = (const float*)d_in[9];
    float* out = (float*)d_out;

    const int has_xyz = (out_size >= BB*KP*3 + BB*KP*CC) ? 1 : 0;
    float* outx = has_xyz ? out : nullptr;
    const int poff = has_xyz ? BB*KP*3 : 0;

    const int fps_smem  = 3*NPT*(int)sizeof(float) + 16*(int)sizeof(unsigned long long);
    const int knn_smem  = 4*NPT*(int)sizeof(float);
    const int g1_smem   = (CIN*SAST + CIN*CC)*(int)sizeof(float);
    const int g2_smem   = (64*SAST + 64*CC)*(int)sizeof(float);
    cudaFuncSetAttribute(fps_kernel,  cudaFuncAttributeMaxDynamicSharedMemorySize, fps_smem);
    cudaFuncSetAttribute(knn_kernel,  cudaFuncAttributeMaxDynamicSharedMemorySize, knn_smem);
    cudaFuncSetAttribute(gemm1_kernel,cudaFuncAttributeMaxDynamicSharedMemorySize, g1_smem);
    cudaFuncSetAttribute(gemm2_kernel,cudaFuncAttributeMaxDynamicSharedMemorySize, g2_smem);

    // local order: fps at slot 3 -> ncu captures fps this round
    wt1_kernel<<<1, 256>>>(W1);
    wt2_kernel<<<1, 256>>>(W2);
    zz_kernel<<<64, 256>>>();
    fps_kernel<<<BB, 256, fps_smem>>>(xyz, outx);
    knn_kernel<<<(BB*KP)/8, 256, knn_smem>>>(xyz);
    gemm1_kernel<<<MT/128, 256, g1_smem>>>(xyz, points, b1);
    bnfin_kernel<<<CC, 256>>>(0, g1, be1);
    gemm2_kernel<<<MT/128, 256, g2_smem>>>(b2);
    bnfin_kernel<<<CC, 256>>>(1, g2, be2);
    final_kernel<<<BB*KP, 128>>>(out, poff);
}